// round 3
// baseline (speedup 1.0000x reference)
#include <cuda_runtime.h>
#include <math.h>

#define NN 200000
#define NE 6400000
#define NG 64
#define NB_SCAN 782   // ceil(NN/256)

// ---- device scratch (static, no runtime allocation) ----
__device__ int    g_count[NN];      // in-degree
__device__ int    g_cursor[NN];     // scatter cursor
__device__ int    g_off[NN];        // CSR offsets (exclusive scan of count)
__device__ int    g_bsum[1024];     // scan block sums
__device__ int    g_srcs[NE];       // src ids sorted by dst
__device__ float4 g_msg[NE];        // edge features sorted by dst
__device__ float  g_nf8[NN * 8];    // node_feat padded to 8 floats/row
__device__ float  g_h1[NN * 32];    // layer-1 output
__device__ float  g_pooled[NG * 32];

// ---------------- setup: zero scratch + pad node features ----------------
__global__ void setup_kernel(const float* __restrict__ node_feat) {
    int i = blockIdx.x * blockDim.x + threadIdx.x;
    if (i < NN * 8) {
        int n = i >> 3, k = i & 7;
        g_nf8[i] = (k < 7) ? node_feat[n * 7 + k] : 0.0f;
    }
    if (i < NN) { g_count[i] = 0; g_cursor[i] = 0; }
    if (i < NG * 32) g_pooled[i] = 0.0f;
}

// ---------------- counting sort by dst ----------------
__global__ void hist_kernel(const int* __restrict__ dst) {
    int e = blockIdx.x * blockDim.x + threadIdx.x;
    if (e >= NE) return;
    atomicAdd(&g_count[dst[e]], 1);
}

__global__ void scan_local_kernel() {
    __shared__ int s[256];
    int t = threadIdx.x;
    int i = blockIdx.x * 256 + t;
    int v = (i < NN) ? g_count[i] : 0;
    s[t] = v;
    __syncthreads();
    for (int off = 1; off < 256; off <<= 1) {
        int add = (t >= off) ? s[t - off] : 0;
        __syncthreads();
        s[t] += add;
        __syncthreads();
    }
    if (i < NN) g_off[i] = s[t] - v;            // exclusive
    if (t == 255) g_bsum[blockIdx.x] = s[255];  // block total
}

__global__ void scan_bsums_kernel() {
    __shared__ int s[1024];
    int t = threadIdx.x;
    int v = (t < NB_SCAN) ? g_bsum[t] : 0;
    s[t] = v;
    __syncthreads();
    for (int off = 1; off < 1024; off <<= 1) {
        int add = (t >= off) ? s[t - off] : 0;
        __syncthreads();
        s[t] += add;
        __syncthreads();
    }
    if (t < NB_SCAN) g_bsum[t] = s[t] - v;      // exclusive
}

__global__ void scan_add_kernel() {
    int i = blockIdx.x * 256 + threadIdx.x;
    if (i < NN) g_off[i] += g_bsum[blockIdx.x];
}

// scatter: write sorted src id AND sorted edge-feature payload
__global__ void scatter_kernel(const int* __restrict__ src,
                               const int* __restrict__ dst,
                               const float4* __restrict__ ef4) {
    int e = blockIdx.x * blockDim.x + threadIdx.x;
    if (e >= NE) return;
    int d = dst[e];
    int pos = g_off[d] + atomicAdd(&g_cursor[d], 1);
    g_srcs[pos] = src[e];
    g_msg[pos]  = ef4[e];
}

// ---------------- layer 1: gather-reduce + MLP (warp per node) ----------------
__global__ void node1_kernel(const float* __restrict__ W1a, const float* __restrict__ b1a,
                             const float* __restrict__ W1b, const float* __restrict__ b1b) {
    __shared__ float sW1a[11 * 32];
    __shared__ float sW1b[32 * 32];
    __shared__ float sb1a[32];
    __shared__ float sb1b[32];
    int tid = threadIdx.x;
    for (int k = tid; k < 11 * 32; k += blockDim.x) sW1a[k] = W1a[k];
    for (int k = tid; k < 32 * 32; k += blockDim.x) sW1b[k] = W1b[k];
    if (tid < 32) { sb1a[tid] = b1a[tid]; sb1b[tid] = b1b[tid]; }
    __syncthreads();

    int warp = tid >> 5;
    int lane = tid & 31;
    int n = blockIdx.x * (blockDim.x >> 5) + warp;
    if (n >= NN) return;

    int start = g_off[n];
    int deg   = g_count[n];

    float acc[11];
#pragma unroll
    for (int k = 0; k < 11; k++) acc[k] = 0.0f;

    const float4* nf4 = (const float4*)g_nf8;
    for (int j = lane; j < deg; j += 32) {
        int    s = g_srcs[start + j];      // sequential, coalesced
        float4 m = g_msg[start + j];       // sequential, coalesced
        acc[0] += m.x; acc[1] += m.y; acc[2] += m.z; acc[3] += m.w;
        float4 a = nf4[s * 2];             // L2-resident gather
        float4 b = nf4[s * 2 + 1];
        acc[4] += a.x; acc[5] += a.y; acc[6] += a.z; acc[7] += a.w;
        acc[8] += b.x; acc[9] += b.y; acc[10] += b.z;
    }

#pragma unroll
    for (int off = 16; off; off >>= 1) {
#pragma unroll
        for (int k = 0; k < 11; k++)
            acc[k] += __shfl_xor_sync(0xffffffffu, acc[k], off);
    }

    float invd = 1.0f / fmaxf((float)deg, 1.0f);

    float y = sb1a[lane];
#pragma unroll
    for (int k = 0; k < 11; k++)
        y = fmaf(acc[k] * invd, sW1a[k * 32 + lane], y);
    y = fmaxf(y, 0.0f);

    float z = sb1b[lane];
#pragma unroll
    for (int k = 0; k < 32; k++) {
        float yk = __shfl_sync(0xffffffffu, y, k);
        z = fmaf(yk, sW1b[k * 32 + lane], z);
    }
    z = fmaxf(z, 0.0f);

    g_h1[n * 32 + lane] = z;
}

// ---------------- layer 2: gather-reduce + MLP + pool (warp per node) ----------------
__global__ void node2_kernel(const float* __restrict__ W2a, const float* __restrict__ b2a,
                             const float* __restrict__ W2b, const float* __restrict__ b2b,
                             const int* __restrict__ graph_ids) {
    __shared__ float sW2a[32 * 32];
    __shared__ float sW2b[32 * 32];
    __shared__ float sb2a[32];
    __shared__ float sb2b[32];
    int tid = threadIdx.x;
    for (int k = tid; k < 32 * 32; k += blockDim.x) { sW2a[k] = W2a[k]; sW2b[k] = W2b[k]; }
    if (tid < 32) { sb2a[tid] = b2a[tid]; sb2b[tid] = b2b[tid]; }
    __syncthreads();

    int warp = tid >> 5;
    int lane = tid & 31;
    int n = blockIdx.x * (blockDim.x >> 5) + warp;
    if (n >= NN) return;

    int start = g_off[n];
    int deg   = g_count[n];

    float acc0 = 0.0f, acc1 = 0.0f, acc2 = 0.0f, acc3 = 0.0f;
    int j = 0;
    for (; j + 4 <= deg; j += 4) {
        int s0 = g_srcs[start + j + 0];    // warp-broadcast, L1-cached
        int s1 = g_srcs[start + j + 1];
        int s2 = g_srcs[start + j + 2];
        int s3 = g_srcs[start + j + 3];
        acc0 += g_h1[s0 * 32 + lane];      // 128B coalesced L2 gathers
        acc1 += g_h1[s1 * 32 + lane];
        acc2 += g_h1[s2 * 32 + lane];
        acc3 += g_h1[s3 * 32 + lane];
    }
    for (; j < deg; j++) {
        int s = g_srcs[start + j];
        acc0 += g_h1[s * 32 + lane];
    }
    float x = ((acc0 + acc1) + (acc2 + acc3)) / fmaxf((float)deg, 1.0f);

    float y = sb2a[lane];
#pragma unroll
    for (int k = 0; k < 32; k++) {
        float xk = __shfl_sync(0xffffffffu, x, k);
        y = fmaf(xk, sW2a[k * 32 + lane], y);
    }
    y = fmaxf(y, 0.0f);

    float z = sb2b[lane];
#pragma unroll
    for (int k = 0; k < 32; k++) {
        float yk = __shfl_sync(0xffffffffu, y, k);
        z = fmaf(yk, sW2b[k * 32 + lane], z);
    }
    z = fmaxf(z, 0.0f);  // >= 0 -> int-compare atomicMax is order-safe

    int g = graph_ids[n];
    atomicMax((int*)&g_pooled[g * 32 + lane], __float_as_int(z));
}

// ---------------- classifier head ----------------
__global__ void head_kernel(const float* __restrict__ Wm1, const float* __restrict__ bm1,
                            const float* __restrict__ Wm2, const float* __restrict__ bm2,
                            float* __restrict__ out) {
    int g = threadIdx.x;
    if (g >= NG) return;
    float p[32];
#pragma unroll
    for (int k = 0; k < 32; k++) p[k] = g_pooled[g * 32 + k];
    float hid[16];
#pragma unroll
    for (int jj = 0; jj < 16; jj++) {
        float a = bm1[jj];
#pragma unroll
        for (int k = 0; k < 32; k++) a = fmaf(p[k], Wm1[k * 16 + jj], a);
        hid[jj] = fmaxf(a, 0.0f);
    }
    float l0 = bm2[0], l1 = bm2[1];
#pragma unroll
    for (int jj = 0; jj < 16; jj++) {
        l0 = fmaf(hid[jj], Wm2[jj * 2 + 0], l0);
        l1 = fmaf(hid[jj], Wm2[jj * 2 + 1], l1);
    }
    float m = fmaxf(l0, l1);
    float e0 = expf(l0 - m);
    float e1 = expf(l1 - m);
    float inv = 1.0f / (e0 + e1);
    out[g * 2 + 0] = e0 * inv;
    out[g * 2 + 1] = e1 * inv;
}

extern "C" void kernel_launch(void* const* d_in, const int* in_sizes, int n_in,
                              void* d_out, int out_size) {
    const float* node_feat = (const float*)d_in[0];
    const float* edge_feat = (const float*)d_in[1];
    const int*   src       = (const int*)d_in[2];
    const int*   dst       = (const int*)d_in[3];
    const int*   graph_ids = (const int*)d_in[4];
    const float* W1a = (const float*)d_in[5];
    const float* b1a = (const float*)d_in[6];
    const float* W1b = (const float*)d_in[7];
    const float* b1b = (const float*)d_in[8];
    const float* W2a = (const float*)d_in[9];
    const float* b2a = (const float*)d_in[10];
    const float* W2b = (const float*)d_in[11];
    const float* b2b = (const float*)d_in[12];
    const float* Wm1 = (const float*)d_in[13];
    const float* bm1 = (const float*)d_in[14];
    const float* Wm2 = (const float*)d_in[15];
    const float* bm2 = (const float*)d_in[16];
    float* out = (float*)d_out;

    setup_kernel<<<(NN * 8 + 255) / 256, 256>>>(node_feat);
    hist_kernel<<<NE / 256, 256>>>(dst);
    scan_local_kernel<<<NB_SCAN, 256>>>();
    scan_bsums_kernel<<<1, 1024>>>();
    scan_add_kernel<<<NB_SCAN, 256>>>();
    scatter_kernel<<<NE / 256, 256>>>(src, dst, (const float4*)edge_feat);
    node1_kernel<<<NN / 8, 256>>>(W1a, b1a, W1b, b1b);
    node2_kernel<<<NN / 8, 256>>>(W2a, b2a, W2b, b2b, graph_ids);
    head_kernel<<<1, 64>>>(Wm1, bm1, Wm2, bm2, out);
}

// round 4
// speedup vs baseline: 1.0226x; 1.0226x over previous
#include <cuda_runtime.h>
#include <cuda_fp16.h>
#include <math.h>

#define NN 200000
#define NE 6400000
#define NG 64
#define NB_SCAN 782   // ceil(NN/256)

// ---- device scratch (static, no runtime allocation) ----
__device__ int    g_count[NN];       // in-degree
__device__ int    g_cursor[NN];      // scatter cursor
__device__ int    g_off[NN];         // CSR offsets (full exclusive scan)
__device__ int    g_bsum[1024];      // scan block totals
__device__ int    g_scan_done;       // scan sync counter
__device__ int2   g_sorted[NE];      // (eid, src) sorted by dst
__device__ float  g_nf8[NN * 8];     // node_feat padded to 8 floats/row
__device__ __half g_h1h[NN * 32];    // layer-1 output (fp16)
__device__ float  g_pooled[NG * 32];

// ---------------- setup: zero scratch + pad node features ----------------
__global__ void setup_kernel(const float* __restrict__ node_feat) {
    int i = blockIdx.x * blockDim.x + threadIdx.x;
    if (i < NN * 8) {
        int n = i >> 3, k = i & 7;
        g_nf8[i] = (k < 7) ? node_feat[n * 7 + k] : 0.0f;
    }
    if (i < NN) { g_count[i] = 0; g_cursor[i] = 0; }
    if (i < NG * 32) g_pooled[i] = 0.0f;
    if (i == 0) g_scan_done = 0;
}

// ---------------- histogram of dst (4 edges per thread) ----------------
__global__ void hist_kernel(const int4* __restrict__ dst4) {
    int i = blockIdx.x * blockDim.x + threadIdx.x;
    if (i >= NE / 4) return;
    int4 d = dst4[i];
    atomicAdd(&g_count[d.x], 1);
    atomicAdd(&g_count[d.y], 1);
    atomicAdd(&g_count[d.z], 1);
    atomicAdd(&g_count[d.w], 1);
}

// ---------------- single-kernel exclusive scan (all blocks resident) ----------------
__global__ void scan_kernel() {
    __shared__ int s[256];
    int t = threadIdx.x;
    int b = blockIdx.x;
    int i = b * 256 + t;
    int v = (i < NN) ? g_count[i] : 0;
    s[t] = v;
    __syncthreads();
    for (int off = 1; off < 256; off <<= 1) {
        int add = (t >= off) ? s[t - off] : 0;
        __syncthreads();
        s[t] += add;
        __syncthreads();
    }
    int local_excl = s[t] - v;
    if (t == 255) {
        g_bsum[b] = s[255];
        __threadfence();
        atomicAdd(&g_scan_done, 1);
    }
    // wait for all blocks to publish (782 blocks <= resident capacity)
    if (t == 0) {
        while (atomicAdd(&g_scan_done, 0) < NB_SCAN) { }
    }
    __syncthreads();
    // each block sums totals of all preceding blocks
    int pre = 0;
    for (int k = t; k < b; k += 256) pre += g_bsum[k];
    s[t] = pre;
    __syncthreads();
    for (int o = 128; o; o >>= 1) {
        if (t < o) s[t] += s[t + o];
        __syncthreads();
    }
    if (i < NN) g_off[i] = s[0] + local_excl;
}

// ---------------- scatter: build (eid, src) sorted by dst ----------------
__global__ void scatter_kernel(const int4* __restrict__ src4,
                               const int4* __restrict__ dst4) {
    int i = blockIdx.x * blockDim.x + threadIdx.x;
    if (i >= NE / 4) return;
    int4 s = src4[i];
    int4 d = dst4[i];
    int e = i * 4;
    int p0 = g_off[d.x] + atomicAdd(&g_cursor[d.x], 1);
    g_sorted[p0] = make_int2(e + 0, s.x);
    int p1 = g_off[d.y] + atomicAdd(&g_cursor[d.y], 1);
    g_sorted[p1] = make_int2(e + 1, s.y);
    int p2 = g_off[d.z] + atomicAdd(&g_cursor[d.z], 1);
    g_sorted[p2] = make_int2(e + 2, s.z);
    int p3 = g_off[d.w] + atomicAdd(&g_cursor[d.w], 1);
    g_sorted[p3] = make_int2(e + 3, s.w);
}

// ---------------- layer 1: gather-reduce + MLP (warp per node) ----------------
__global__ void node1_kernel(const float4* __restrict__ ef4,
                             const float* __restrict__ W1a, const float* __restrict__ b1a,
                             const float* __restrict__ W1b, const float* __restrict__ b1b) {
    __shared__ float sW1a[11 * 32];
    __shared__ float sW1b[32 * 32];
    __shared__ float sb1a[32];
    __shared__ float sb1b[32];
    int tid = threadIdx.x;
    for (int k = tid; k < 11 * 32; k += blockDim.x) sW1a[k] = W1a[k];
    for (int k = tid; k < 32 * 32; k += blockDim.x) sW1b[k] = W1b[k];
    if (tid < 32) { sb1a[tid] = b1a[tid]; sb1b[tid] = b1b[tid]; }
    __syncthreads();

    int warp = tid >> 5;
    int lane = tid & 31;
    int n = blockIdx.x * (blockDim.x >> 5) + warp;
    if (n >= NN) return;

    int start = g_off[n];
    int deg   = g_count[n];

    float acc[11];
#pragma unroll
    for (int k = 0; k < 11; k++) acc[k] = 0.0f;

    const float4* nf4 = (const float4*)g_nf8;
    for (int j = lane; j < deg; j += 32) {
        int2 p = g_sorted[start + j];      // sequential, coalesced
        float4 m = __ldg(&ef4[p.x]);       // random 16B gather (DRAM stream)
        acc[0] += m.x; acc[1] += m.y; acc[2] += m.z; acc[3] += m.w;
        float4 a = __ldg(&nf4[p.y * 2]);   // L2-resident 32B gather
        float4 b = __ldg(&nf4[p.y * 2 + 1]);
        acc[4] += a.x; acc[5] += a.y; acc[6] += a.z; acc[7] += a.w;
        acc[8] += b.x; acc[9] += b.y; acc[10] += b.z;
    }

#pragma unroll
    for (int off = 16; off; off >>= 1) {
#pragma unroll
        for (int k = 0; k < 11; k++)
            acc[k] += __shfl_xor_sync(0xffffffffu, acc[k], off);
    }

    float invd = 1.0f / fmaxf((float)deg, 1.0f);

    float y = sb1a[lane];
#pragma unroll
    for (int k = 0; k < 11; k++)
        y = fmaf(acc[k] * invd, sW1a[k * 32 + lane], y);
    y = fmaxf(y, 0.0f);

    float z = sb1b[lane];
#pragma unroll
    for (int k = 0; k < 32; k++) {
        float yk = __shfl_sync(0xffffffffu, y, k);
        z = fmaf(yk, sW1b[k * 32 + lane], z);
    }
    z = fmaxf(z, 0.0f);

    g_h1h[n * 32 + lane] = __float2half_rn(z);
}

// ---------------- layer 2: fp16 gather-reduce + MLP + pool (warp per node) ----------------
__global__ void node2_kernel(const float* __restrict__ W2a, const float* __restrict__ b2a,
                             const float* __restrict__ W2b, const float* __restrict__ b2b,
                             const int* __restrict__ graph_ids) {
    __shared__ float sW2a[32 * 32];
    __shared__ float sW2b[32 * 32];
    __shared__ float sb2a[32];
    __shared__ float sb2b[32];
    int tid = threadIdx.x;
    for (int k = tid; k < 32 * 32; k += blockDim.x) { sW2a[k] = W2a[k]; sW2b[k] = W2b[k]; }
    if (tid < 32) { sb2a[tid] = b2a[tid]; sb2b[tid] = b2b[tid]; }
    __syncthreads();

    int warp = tid >> 5;
    int lane = tid & 31;
    int n = blockIdx.x * (blockDim.x >> 5) + warp;
    if (n >= NN) return;

    int start = g_off[n];
    int deg   = g_count[n];

    float acc0 = 0.0f, acc1 = 0.0f, acc2 = 0.0f, acc3 = 0.0f;
    int j = 0;
    for (; j + 4 <= deg; j += 4) {
        int s0 = g_sorted[start + j + 0].y;  // broadcast, L1
        int s1 = g_sorted[start + j + 1].y;
        int s2 = g_sorted[start + j + 2].y;
        int s3 = g_sorted[start + j + 3].y;
        acc0 += __half2float(__ldg(&g_h1h[s0 * 32 + lane]));  // 64B coalesced L2 gathers
        acc1 += __half2float(__ldg(&g_h1h[s1 * 32 + lane]));
        acc2 += __half2float(__ldg(&g_h1h[s2 * 32 + lane]));
        acc3 += __half2float(__ldg(&g_h1h[s3 * 32 + lane]));
    }
    for (; j < deg; j++) {
        int s = g_sorted[start + j].y;
        acc0 += __half2float(__ldg(&g_h1h[s * 32 + lane]));
    }
    float x = ((acc0 + acc1) + (acc2 + acc3)) / fmaxf((float)deg, 1.0f);

    float y = sb2a[lane];
#pragma unroll
    for (int k = 0; k < 32; k++) {
        float xk = __shfl_sync(0xffffffffu, x, k);
        y = fmaf(xk, sW2a[k * 32 + lane], y);
    }
    y = fmaxf(y, 0.0f);

    float z = sb2b[lane];
#pragma unroll
    for (int k = 0; k < 32; k++) {
        float yk = __shfl_sync(0xffffffffu, y, k);
        z = fmaf(yk, sW2b[k * 32 + lane], z);
    }
    z = fmaxf(z, 0.0f);  // >= 0 -> int-compare atomicMax is order-safe

    int g = graph_ids[n];
    atomicMax((int*)&g_pooled[g * 32 + lane], __float_as_int(z));
}

// ---------------- classifier head ----------------
__global__ void head_kernel(const float* __restrict__ Wm1, const float* __restrict__ bm1,
                            const float* __restrict__ Wm2, const float* __restrict__ bm2,
                            float* __restrict__ out) {
    int g = threadIdx.x;
    if (g >= NG) return;
    float p[32];
#pragma unroll
    for (int k = 0; k < 32; k++) p[k] = g_pooled[g * 32 + k];
    float hid[16];
#pragma unroll
    for (int jj = 0; jj < 16; jj++) {
        float a = bm1[jj];
#pragma unroll
        for (int k = 0; k < 32; k++) a = fmaf(p[k], Wm1[k * 16 + jj], a);
        hid[jj] = fmaxf(a, 0.0f);
    }
    float l0 = bm2[0], l1 = bm2[1];
#pragma unroll
    for (int jj = 0; jj < 16; jj++) {
        l0 = fmaf(hid[jj], Wm2[jj * 2 + 0], l0);
        l1 = fmaf(hid[jj], Wm2[jj * 2 + 1], l1);
    }
    float m = fmaxf(l0, l1);
    float e0 = expf(l0 - m);
    float e1 = expf(l1 - m);
    float inv = 1.0f / (e0 + e1);
    out[g * 2 + 0] = e0 * inv;
    out[g * 2 + 1] = e1 * inv;
}

extern "C" void kernel_launch(void* const* d_in, const int* in_sizes, int n_in,
                              void* d_out, int out_size) {
    const float* node_feat = (const float*)d_in[0];
    const float* edge_feat = (const float*)d_in[1];
    const int*   src       = (const int*)d_in[2];
    const int*   dst       = (const int*)d_in[3];
    const int*   graph_ids = (const int*)d_in[4];
    const float* W1a = (const float*)d_in[5];
    const float* b1a = (const float*)d_in[6];
    const float* W1b = (const float*)d_in[7];
    const float* b1b = (const float*)d_in[8];
    const float* W2a = (const float*)d_in[9];
    const float* b2a = (const float*)d_in[10];
    const float* W2b = (const float*)d_in[11];
    const float* b2b = (const float*)d_in[12];
    const float* Wm1 = (const float*)d_in[13];
    const float* bm1 = (const float*)d_in[14];
    const float* Wm2 = (const float*)d_in[15];
    const float* bm2 = (const float*)d_in[16];
    float* out = (float*)d_out;

    setup_kernel<<<(NN * 8 + 255) / 256, 256>>>(node_feat);
    hist_kernel<<<(NE / 4 + 255) / 256, 256>>>((const int4*)dst);
    scan_kernel<<<NB_SCAN, 256>>>();
    scatter_kernel<<<(NE / 4 + 255) / 256, 256>>>((const int4*)src, (const int4*)dst);
    node1_kernel<<<NN / 8, 256>>>((const float4*)edge_feat, W1a, b1a, W1b, b1b);
    node2_kernel<<<NN / 8, 256>>>(W2a, b2a, W2b, b2b, graph_ids);
    head_kernel<<<1, 64>>>(Wm1, bm1, Wm2, bm2, out);
}